// round 2
// baseline (speedup 1.0000x reference)
#include <cuda_runtime.h>
#include <cstdint>

// ---------------------------------------------------------------------------
// CrossAttention: B=8, Nt=1024, N=1024, D=768, H=8, HD=96, CLS=20, L=1044
// Output = softmax2( splitsoftmax(QK^T*scale) + bernoulli_mask*NEG ) @ V @ Wproj + b
// Query rows 0..19 (cls) are dropped by the final slice -> never computed; Wcls unused.
// Mask = JAX threefry2x32, key (0,42), PARTITIONABLE stream:
//   per-element counter (hi=0, lo=flat_idx), bits = out0 ^ out1.
// ---------------------------------------------------------------------------

#define DEV_INLINE __device__ __forceinline__

constexpr int   Bsz  = 8;
constexpr int   NtQ  = 1024;
constexpr int   Nk   = 1024;
constexpr int   Dm   = 768;
constexpr int   HD   = 96;
constexpr float QSCALE = 0.10206207261596577f;   // 96^-0.5

// ---------------- scratch (static device globals; no allocation) -----------
__device__ float g_q [Bsz * NtQ * Dm];            //  25 MB
__device__ float g_kv[Bsz * Nk * 2 * Dm];         //  50 MB
__device__ float g_ao[Bsz * NtQ * Dm];            //  25 MB
__device__ float g_s [(size_t)64 * 1024 * 1024];  // 268 MB  [bh][q'][n] logits

// ---------------------------------------------------------------------------
// JAX threefry2x32, key = (0, 42)
// ---------------------------------------------------------------------------
DEV_INLINE uint32_t rotl32(uint32_t x, int d) { return __funnelshift_l(x, x, d); }

DEV_INLINE uint2 threefry2x32_k42(uint32_t x0, uint32_t x1) {
    const uint32_t ks0 = 0u, ks1 = 42u, ks2 = 0x1BD11BF0u; // 0x1BD11BDA ^ 0 ^ 42
    x0 += ks0; x1 += ks1;
    // block 1 (13,15,26,6)
    x0 += x1; x1 = rotl32(x1, 13); x1 ^= x0;
    x0 += x1; x1 = rotl32(x1, 15); x1 ^= x0;
    x0 += x1; x1 = rotl32(x1, 26); x1 ^= x0;
    x0 += x1; x1 = rotl32(x1,  6); x1 ^= x0;
    x0 += ks1; x1 += ks2 + 1u;
    // block 2 (17,29,16,24)
    x0 += x1; x1 = rotl32(x1, 17); x1 ^= x0;
    x0 += x1; x1 = rotl32(x1, 29); x1 ^= x0;
    x0 += x1; x1 = rotl32(x1, 16); x1 ^= x0;
    x0 += x1; x1 = rotl32(x1, 24); x1 ^= x0;
    x0 += ks2; x1 += ks0 + 2u;
    // block 3 (13,15,26,6)
    x0 += x1; x1 = rotl32(x1, 13); x1 ^= x0;
    x0 += x1; x1 = rotl32(x1, 15); x1 ^= x0;
    x0 += x1; x1 = rotl32(x1, 26); x1 ^= x0;
    x0 += x1; x1 = rotl32(x1,  6); x1 ^= x0;
    x0 += ks0; x1 += ks1 + 3u;
    // block 4 (17,29,16,24)
    x0 += x1; x1 = rotl32(x1, 17); x1 ^= x0;
    x0 += x1; x1 = rotl32(x1, 29); x1 ^= x0;
    x0 += x1; x1 = rotl32(x1, 16); x1 ^= x0;
    x0 += x1; x1 = rotl32(x1, 24); x1 ^= x0;
    x0 += ks1; x1 += ks2 + 4u;
    // block 5 (13,15,26,6)
    x0 += x1; x1 = rotl32(x1, 13); x1 ^= x0;
    x0 += x1; x1 = rotl32(x1, 15); x1 ^= x0;
    x0 += x1; x1 = rotl32(x1, 26); x1 ^= x0;
    x0 += x1; x1 = rotl32(x1,  6); x1 ^= x0;
    x0 += ks2; x1 += ks0 + 5u;
    return make_uint2(x0, x1);
}

// partitionable stream, 32-bit draw, flat index fi (< 2^32 here)
DEV_INLINE bool masked_at(uint32_t fi) {
    uint2 r = threefry2x32_k42(0u, fi);
    uint32_t bits = r.x ^ r.y;
    float u = __uint_as_float(0x3f800000u | (bits >> 9)) - 1.0f;
    return u < 0.3f;
}

// ---------------------------------------------------------------------------
// SGEMM: C[M,N] = A[M,K] @ B[K,N] (+bias). 128x128x8 tile, 256 thr, 8x8 micro.
// ---------------------------------------------------------------------------
template<bool BIAS>
__global__ __launch_bounds__(256) void sgemm_kernel(
    const float* __restrict__ A, const float* __restrict__ Bm,
    const float* __restrict__ bias, float* __restrict__ C,
    int M, int N, int K)
{
    __shared__ float As[8][128];   // transposed A tile
    __shared__ float Bs[8][128];
    const int tid = threadIdx.x;
    const int tx = tid & 15, ty = tid >> 4;
    const int bx = blockIdx.x, by = blockIdx.y;

    const float* Ap = A + (size_t)(by * 128) * K;
    const float* Bp = Bm + bx * 128;

    float acc[8][8];
#pragma unroll
    for (int i = 0; i < 8; i++)
#pragma unroll
        for (int j = 0; j < 8; j++) acc[i][j] = 0.f;

    const int arow = tid >> 1, ac4 = (tid & 1) * 4;
    const int brow = tid >> 5, bc4 = (tid & 31) * 4;

    for (int k0 = 0; k0 < K; k0 += 8) {
        float4 av = *reinterpret_cast<const float4*>(Ap + (size_t)arow * K + k0 + ac4);
        As[ac4 + 0][arow] = av.x;
        As[ac4 + 1][arow] = av.y;
        As[ac4 + 2][arow] = av.z;
        As[ac4 + 3][arow] = av.w;
        *reinterpret_cast<float4*>(&Bs[brow][bc4]) =
            *reinterpret_cast<const float4*>(Bp + (size_t)(k0 + brow) * N + bc4);
        __syncthreads();
#pragma unroll
        for (int kk = 0; kk < 8; kk++) {
            float a0[8], b0[8];
            *reinterpret_cast<float4*>(a0)     = *reinterpret_cast<float4*>(&As[kk][ty * 8]);
            *reinterpret_cast<float4*>(a0 + 4) = *reinterpret_cast<float4*>(&As[kk][ty * 8 + 4]);
            *reinterpret_cast<float4*>(b0)     = *reinterpret_cast<float4*>(&Bs[kk][tx * 8]);
            *reinterpret_cast<float4*>(b0 + 4) = *reinterpret_cast<float4*>(&Bs[kk][tx * 8 + 4]);
#pragma unroll
            for (int i = 0; i < 8; i++)
#pragma unroll
                for (int j = 0; j < 8; j++) acc[i][j] += a0[i] * b0[j];
        }
        __syncthreads();
    }

    const int colbase = bx * 128 + tx * 8;
    float bi[8];
#pragma unroll
    for (int j = 0; j < 8; j++) bi[j] = BIAS ? bias[colbase + j] : 0.f;

#pragma unroll
    for (int i = 0; i < 8; i++) {
        size_t row = (size_t)(by * 128 + ty * 8 + i);
        float* cp = C + row * N + colbase;
        float4 v0 = make_float4(acc[i][0] + bi[0], acc[i][1] + bi[1],
                                acc[i][2] + bi[2], acc[i][3] + bi[3]);
        float4 v1 = make_float4(acc[i][4] + bi[4], acc[i][5] + bi[5],
                                acc[i][6] + bi[6], acc[i][7] + bi[7]);
        *reinterpret_cast<float4*>(cp)     = v0;
        *reinterpret_cast<float4*>(cp + 4) = v1;
    }
}

// ---------------------------------------------------------------------------
// Fused attention. grid = (16 qtiles, 64 bh), 256 threads.
// Pass A: S = (Q*scale)K^T -> g_s, online split-softmax stats (m1,z1 | m2,z2)
// Pass B: a = exp(s-m)/z ; e = keep * exp(a-1) ; out = (e V)/sum(e)
// ---------------------------------------------------------------------------
__global__ __launch_bounds__(256, 2) void attn_kernel()
{
    extern __shared__ float sm[];
    float* Qt   = sm;                 // [96][68] transposed, scaled
    float* Kt   = Qt + 96 * 68;       // [96][68] transposed
    float* Vs   = Kt + 96 * 68;       // [64][96]
    float* Ps   = Vs + 64 * 96;       // [64][68]
    float* redm = Ps + 64 * 68;       // [16][64]
    float* redz = redm + 1024;        // [16][64]
    float* m1s  = redz + 1024;        // [64]
    float* z1s  = m1s + 64;
    float* m2s  = z1s + 64;
    float* z2s  = m2s + 64;
    float* zfs  = z2s + 64;

    const int qt = blockIdx.x, bh = blockIdx.y;
    const int b = bh >> 3, h = bh & 7;
    const int tid = threadIdx.x;
    const int tx = tid & 15, ty = tid >> 4;

    // ---- load Q tile (transposed, pre-scaled) ----
    {
        const float* qg = g_q + ((size_t)(b * NtQ + qt * 64)) * Dm + h * HD;
        for (int t = tid; t < 64 * 24; t += 256) {
            int r = t / 24, c4 = t % 24;
            float4 v = *reinterpret_cast<const float4*>(qg + (size_t)r * Dm + c4 * 4);
            Qt[(c4 * 4 + 0) * 68 + r] = v.x * QSCALE;
            Qt[(c4 * 4 + 1) * 68 + r] = v.y * QSCALE;
            Qt[(c4 * 4 + 2) * 68 + r] = v.z * QSCALE;
            Qt[(c4 * 4 + 3) * 68 + r] = v.w * QSCALE;
        }
    }

    float m1p[4], z1p[4], m2p[4], z2p[4];
#pragma unroll
    for (int i = 0; i < 4; i++) { m1p[i] = -1e30f; z1p[i] = 0.f; m2p[i] = -1e30f; z2p[i] = 0.f; }

    float* sg = g_s + ((size_t)(bh * 1024 + qt * 64)) * 1024;

    // ================= PASS A =================
    for (int c = 0; c < 16; c++) {
        __syncthreads();
        const float* kg = g_kv + ((size_t)(b * Nk + c * 64)) * (2 * Dm) + h * HD;
        for (int t = tid; t < 64 * 24; t += 256) {
            int r = t / 24, c4 = t % 24;
            float4 v = *reinterpret_cast<const float4*>(kg + (size_t)r * (2 * Dm) + c4 * 4);
            Kt[(c4 * 4 + 0) * 68 + r] = v.x;
            Kt[(c4 * 4 + 1) * 68 + r] = v.y;
            Kt[(c4 * 4 + 2) * 68 + r] = v.z;
            Kt[(c4 * 4 + 3) * 68 + r] = v.w;
        }
        __syncthreads();

        float s[4][4];
#pragma unroll
        for (int i = 0; i < 4; i++)
#pragma unroll
            for (int j = 0; j < 4; j++) s[i][j] = 0.f;

#pragma unroll 8
        for (int kk = 0; kk < 96; kk++) {
            float4 qv = *reinterpret_cast<const float4*>(&Qt[kk * 68 + ty * 4]);
            float4 kv = *reinterpret_cast<const float4*>(&Kt[kk * 68 + tx * 4]);
            float qa[4] = {qv.x, qv.y, qv.z, qv.w};
            float ka[4] = {kv.x, kv.y, kv.z, kv.w};
#pragma unroll
            for (int i = 0; i < 4; i++)
#pragma unroll
                for (int j = 0; j < 4; j++) s[i][j] += qa[i] * ka[j];
        }

        // store logits
#pragma unroll
        for (int i = 0; i < 4; i++) {
            *reinterpret_cast<float4*>(sg + (size_t)(ty * 4 + i) * 1024 + c * 64 + tx * 4) =
                make_float4(s[i][0], s[i][1], s[i][2], s[i][3]);
        }

        // online stats (this thread's cols are entirely cls (c==0, tx<5) or patch)
        const bool clsth = (c == 0 && tx < 5);
#pragma unroll
        for (int i = 0; i < 4; i++) {
            float lm = fmaxf(fmaxf(s[i][0], s[i][1]), fmaxf(s[i][2], s[i][3]));
            if (clsth) {
                float nm = fmaxf(m1p[i], lm);
                z1p[i] = z1p[i] * expf(m1p[i] - nm)
                       + expf(s[i][0] - nm) + expf(s[i][1] - nm)
                       + expf(s[i][2] - nm) + expf(s[i][3] - nm);
                m1p[i] = nm;
            } else {
                float nm = fmaxf(m2p[i], lm);
                z2p[i] = z2p[i] * expf(m2p[i] - nm)
                       + expf(s[i][0] - nm) + expf(s[i][1] - nm)
                       + expf(s[i][2] - nm) + expf(s[i][3] - nm);
                m2p[i] = nm;
            }
        }
    }

    // ---- combine stats across the 16 tx lanes ----
    __syncthreads();
#pragma unroll
    for (int i = 0; i < 4; i++) { redm[tx * 64 + ty * 4 + i] = m2p[i]; redz[tx * 64 + ty * 4 + i] = z2p[i]; }
    __syncthreads();
    if (tid < 64) {
        float m = -1e30f;
        for (int t = 0; t < 16; t++) m = fmaxf(m, redm[t * 64 + tid]);
        float z = 0.f;
        for (int t = 0; t < 16; t++) z += redz[t * 64 + tid] * expf(redm[t * 64 + tid] - m);
        m2s[tid] = m; z2s[tid] = z;
    }
    __syncthreads();
#pragma unroll
    for (int i = 0; i < 4; i++) {
        bool v = (tx < 5);
        redm[tx * 64 + ty * 4 + i] = v ? m1p[i] : -1e30f;
        redz[tx * 64 + ty * 4 + i] = v ? z1p[i] : 0.f;
    }
    __syncthreads();
    if (tid < 64) {
        float m = -1e30f;
        for (int t = 0; t < 16; t++) m = fmaxf(m, redm[t * 64 + tid]);
        float z = 0.f;
        for (int t = 0; t < 16; t++) z += redz[t * 64 + tid] * expf(redm[t * 64 + tid] - m);
        m1s[tid] = m; z1s[tid] = z;
    }

    // ================= PASS B =================
    float acc[4][6];
#pragma unroll
    for (int i = 0; i < 4; i++)
#pragma unroll
        for (int j = 0; j < 6; j++) acc[i][j] = 0.f;
    float zfp[4] = {0.f, 0.f, 0.f, 0.f};

    for (int c = 0; c < 16; c++) {
        __syncthreads();   // also covers stats visibility on c==0
        const float* vg = g_kv + ((size_t)(b * Nk + c * 64)) * (2 * Dm) + Dm + h * HD;
        for (int t = tid; t < 64 * 24; t += 256) {
            int r = t / 24, c4 = t % 24;
            *reinterpret_cast<float4*>(&Vs[r * 96 + c4 * 4]) =
                *reinterpret_cast<const float4*>(vg + (size_t)r * (2 * Dm) + c4 * 4);
        }

#pragma unroll
        for (int i = 0; i < 4; i++) {
            const int r = ty * 4 + i;
            const uint32_t l = 20u + (uint32_t)(qt * 64 + r);
            float4 sv = *reinterpret_cast<const float4*>(sg + (size_t)r * 1024 + c * 64 + tx * 4);
            float sa[4] = {sv.x, sv.y, sv.z, sv.w};
            const float m1 = m1s[r], z1 = z1s[r], m2 = m2s[r], z2 = z2s[r];
            float e[4];
#pragma unroll
            for (int j = 0; j < 4; j++) {
                const uint32_t n = (uint32_t)(c * 64 + tx * 4 + j);
                const bool iscls = (n < 20u);
                const float a = expf(sa[j] - (iscls ? m1 : m2)) / (iscls ? z1 : z2);
                const uint32_t fi = ((uint32_t)bh * 1044u + l) * 1024u + n;
                e[j] = masked_at(fi) ? 0.0f : expf(a - 1.0f);
                zfp[i] += e[j];
            }
            *reinterpret_cast<float4*>(&Ps[r * 68 + tx * 4]) = make_float4(e[0], e[1], e[2], e[3]);
        }
        __syncthreads();

        // PV: rows ty*4+i, cols tx*6..tx*6+5
#pragma unroll 2
        for (int n = 0; n < 64; n++) {
            float p0 = Ps[(ty * 4 + 0) * 68 + n];
            float p1 = Ps[(ty * 4 + 1) * 68 + n];
            float p2 = Ps[(ty * 4 + 2) * 68 + n];
            float p3 = Ps[(ty * 4 + 3) * 68 + n];
#pragma unroll
            for (int j = 0; j < 6; j++) {
                float vv = Vs[n * 96 + tx * 6 + j];
                acc[0][j] += p0 * vv;
                acc[1][j] += p1 * vv;
                acc[2][j] += p2 * vv;
                acc[3][j] += p3 * vv;
            }
        }
    }

    // ---- zf reduce + write ----
    __syncthreads();
#pragma unroll
    for (int i = 0; i < 4; i++) redz[tx * 64 + ty * 4 + i] = zfp[i];
    __syncthreads();
    if (tid < 64) {
        float z = 0.f;
        for (int t = 0; t < 16; t++) z += redz[t * 64 + tid];
        zfs[tid] = z;
    }
    __syncthreads();

    float* og = g_ao + ((size_t)(b * NtQ + qt * 64)) * Dm + h * HD;
#pragma unroll
    for (int i = 0; i < 4; i++) {
        const float rz = 1.0f / zfs[ty * 4 + i];
#pragma unroll
        for (int j = 0; j < 6; j++)
            og[(size_t)(ty * 4 + i) * Dm + tx * 6 + j] = acc[i][j] * rz;
    }
}

// ---------------------------------------------------------------------------
extern "C" void kernel_launch(void* const* d_in, const int* in_sizes, int n_in,
                              void* d_out, int out_size)
{
    const float* input_query = (const float*)d_in[0];
    const float* input_key   = (const float*)d_in[1];
    const float* Wq          = (const float*)d_in[2];
    const float* Wkv         = (const float*)d_in[3];
    // d_in[4] = Wcls  -- provably unused (cls query rows are sliced away)
    const float* Wproj       = (const float*)d_in[5];
    const float* bproj       = (const float*)d_in[6];
    float* out = (float*)d_out;

    float *qp, *kvp, *aop;
    cudaGetSymbolAddress((void**)&qp,  g_q);
    cudaGetSymbolAddress((void**)&kvp, g_kv);
    cudaGetSymbolAddress((void**)&aop, g_ao);

    const int smem_bytes = (96 * 68 * 2 + 64 * 96 + 64 * 68 + 1024 * 2 + 5 * 64) * 4;
    cudaFuncSetAttribute(attn_kernel, cudaFuncAttributeMaxDynamicSharedMemorySize, smem_bytes);

    // q = input_query @ Wq          [8192,768]
    sgemm_kernel<false><<<dim3(6, 64), 256>>>(input_query, Wq, nullptr, qp, 8192, 768, 768);
    // kv = input_key @ Wkv          [8192,1536]
    sgemm_kernel<false><<<dim3(12, 64), 256>>>(input_key, Wkv, nullptr, kvp, 8192, 1536, 768);
    // fused double-softmax attention
    attn_kernel<<<dim3(16, 64), 256, smem_bytes>>>();
    // out = attn_out @ Wproj + b    [8192,768]
    sgemm_kernel<true><<<dim3(6, 64), 256>>>(aop, Wproj, bproj, out, 8192, 768, 768);
}

// round 4
// speedup vs baseline: 1.3430x; 1.3430x over previous
#include <cuda_runtime.h>
#include <cuda_bf16.h>
#include <cstdint>

// ---------------------------------------------------------------------------
// CrossAttention: B=8, Nt=1024, N=1024, D=768, H=8, HD=96, CLS=20, L=1044
// GEMMs on mma.sync bf16 (hi/lo split, 3-term) -- tcgen05 unavailable: the
// harness targets plain sm_103 (no 'a' suffix), which gates off tcgen05.
// Attention fp32 (unchanged, known-good).
// ---------------------------------------------------------------------------

#define DEV_INLINE __device__ __forceinline__

constexpr int   Bsz  = 8;
constexpr int   NtQ  = 1024;
constexpr int   Nk   = 1024;
constexpr int   Dm   = 768;
constexpr int   HD   = 96;
constexpr float QSCALE = 0.10206207261596577f;   // 96^-0.5

// ---------------- scratch (static device globals; no allocation) -----------
__device__ float g_q [Bsz * NtQ * Dm];            //  25 MB
__device__ float g_kv[Bsz * Nk * 2 * Dm];         //  50 MB
__device__ float g_ao[Bsz * NtQ * Dm];            //  25 MB
__device__ float g_s [(size_t)64 * 1024 * 1024];  // 268 MB  [bh][q'][n] logits

// ===========================================================================
//                       mma.sync bf16 GEMM
//  C[M,N] = A[M,K] @ B[K,N] (+bias), fp32 in/out.
//  Split trick: x = hi(bf16) + lo(bf16);  C = Ah*Bh + Ah*Bl + Al*Bh.
//  CTA 128x128, K-chunk 32, 8 warps of 64x32, occupancy 2.
// ===========================================================================

// packed bf16x2 split of an fp32 pair (x -> low half, y -> high half)
DEV_INLINE void split2(float x, float y, uint32_t& hi, uint32_t& lo) {
    __nv_bfloat162 h = __floats2bfloat162_rn(x, y);
    float hx = __bfloat162float(h.x), hy = __bfloat162float(h.y);
    __nv_bfloat162 l = __floats2bfloat162_rn(x - hx, y - hy);
    hi = *reinterpret_cast<uint32_t*>(&h);
    lo = *reinterpret_cast<uint32_t*>(&l);
}

DEV_INLINE void mma16816(float* d, const uint32_t* a, const uint32_t* b) {
    asm volatile(
        "mma.sync.aligned.m16n8k16.row.col.f32.bf16.bf16.f32 "
        "{%0,%1,%2,%3}, {%4,%5,%6,%7}, {%8,%9}, {%0,%1,%2,%3};"
        : "+f"(d[0]), "+f"(d[1]), "+f"(d[2]), "+f"(d[3])
        : "r"(a[0]), "r"(a[1]), "r"(a[2]), "r"(a[3]), "r"(b[0]), "r"(b[1]));
}

// SMEM row stride: 40 bf16 = 80 B = 20 words  (conflict-free for frag loads)
constexpr int SSTR = 20;   // uint32 words per row

template<bool BIAS>
__global__ __launch_bounds__(256, 2) void mma_gemm(
    const float* __restrict__ A, const float* __restrict__ Bm,
    const float* __restrict__ bias, float* __restrict__ C,
    int M, int N, int K)
{
    __shared__ uint32_t Ah[128 * SSTR];
    __shared__ uint32_t Al[128 * SSTR];
    __shared__ uint32_t Bh[128 * SSTR];
    __shared__ uint32_t Bl[128 * SSTR];

    const int tid  = threadIdx.x;
    const int lane = tid & 31;
    const int wid  = tid >> 5;
    const int wy   = wid >> 2;          // 0..1  -> m offset wy*64
    const int wx   = wid & 3;           // 0..3  -> n offset wx*32

    const int m0 = blockIdx.y * 128;
    const int n0 = blockIdx.x * 128;

    float acc[4][4][4];                 // [m-tile][n-tile][frag]
#pragma unroll
    for (int i = 0; i < 4; i++)
#pragma unroll
        for (int j = 0; j < 4; j++)
#pragma unroll
            for (int q = 0; q < 4; q++) acc[i][j][q] = 0.f;

    const int gq = lane >> 2;           // group id 0..7
    const int gt = lane & 3;            // 0..3

    for (int kc = 0; kc < K; kc += 32) {
        __syncthreads();
        // ---- A chunk [128m x 32k] : 1024 float4, 4 per thread ----
#pragma unroll
        for (int p = 0; p < 4; p++) {
            const int idx = tid + p * 256;
            const int row = idx >> 3, c4 = idx & 7;
            float4 v = *reinterpret_cast<const float4*>(
                A + (size_t)(m0 + row) * K + kc + c4 * 4);
            uint32_t h01, l01, h23, l23;
            split2(v.x, v.y, h01, l01);
            split2(v.z, v.w, h23, l23);
            const int w = row * SSTR + c4 * 2;
            Ah[w] = h01; Ah[w + 1] = h23;
            Al[w] = l01; Al[w + 1] = l23;
        }
        // ---- B chunk transposed: Bt[n][k], n = tid&127, k half by tid>>7 ----
        {
            const int n  = tid & 127;
            const int kq = tid >> 7;    // 0..1
            const float* Bg = Bm + (size_t)kc * N + n0 + n;
#pragma unroll
            for (int p = 0; p < 8; p++) {
                const int k = kq * 16 + p * 2;
                float x = Bg[(size_t)k * N];
                float y = Bg[(size_t)(k + 1) * N];
                uint32_t h, l;
                split2(x, y, h, l);
                const int w = n * SSTR + k / 2;
                Bh[w] = h; Bl[w] = l;
            }
        }
        __syncthreads();

        // ---- compute: 2 k16 steps ----
#pragma unroll
        for (int ks = 0; ks < 2; ks++) {
            uint32_t ah[4][4], al[4][4];
#pragma unroll
            for (int mt = 0; mt < 4; mt++) {
                const int r  = wy * 64 + mt * 16 + gq;
                const int cw = ks * 8 + gt;           // word index of col pair
                ah[mt][0] = Ah[r * SSTR + cw];
                ah[mt][1] = Ah[(r + 8) * SSTR + cw];
                ah[mt][2] = Ah[r * SSTR + cw + 4];
                ah[mt][3] = Ah[(r + 8) * SSTR + cw + 4];
                al[mt][0] = Al[r * SSTR + cw];
                al[mt][1] = Al[(r + 8) * SSTR + cw];
                al[mt][2] = Al[r * SSTR + cw + 4];
                al[mt][3] = Al[(r + 8) * SSTR + cw + 4];
            }
#pragma unroll
            for (int nt = 0; nt < 4; nt++) {
                const int n  = wx * 32 + nt * 8 + gq;
                const int kw = ks * 8 + gt;
                uint32_t bh[2], bl[2];
                bh[0] = Bh[n * SSTR + kw];
                bh[1] = Bh[n * SSTR + kw + 4];
                bl[0] = Bl[n * SSTR + kw];
                bl[1] = Bl[n * SSTR + kw + 4];
#pragma unroll
                for (int mt = 0; mt < 4; mt++) {
                    mma16816(acc[mt][nt], ah[mt], bh);
                    mma16816(acc[mt][nt], ah[mt], bl);
                    mma16816(acc[mt][nt], al[mt], bh);
                }
            }
        }
    }

    // ---- epilogue: direct stores (float2 per frag half) ----
#pragma unroll
    for (int mt = 0; mt < 4; mt++) {
        const int r0 = m0 + wy * 64 + mt * 16 + gq;
#pragma unroll
        for (int nt = 0; nt < 4; nt++) {
            const int col = n0 + wx * 32 + nt * 8 + gt * 2;
            float bx = 0.f, by = 0.f;
            if (BIAS) { bx = bias[col]; by = bias[col + 1]; }
            *reinterpret_cast<float2*>(C + (size_t)r0 * N + col) =
                make_float2(acc[mt][nt][0] + bx, acc[mt][nt][1] + by);
            *reinterpret_cast<float2*>(C + (size_t)(r0 + 8) * N + col) =
                make_float2(acc[mt][nt][2] + bx, acc[mt][nt][3] + by);
        }
    }
}

// ===========================================================================
//                      threefry mask (JAX partitionable)
// ===========================================================================
DEV_INLINE uint32_t rotl32(uint32_t x, int d) { return __funnelshift_l(x, x, d); }

DEV_INLINE uint2 threefry2x32_k42(uint32_t x0, uint32_t x1) {
    const uint32_t ks1 = 42u, ks2 = 0x1BD11BF0u;
    x0 += 0u; x1 += ks1;
    x0 += x1; x1 = rotl32(x1, 13); x1 ^= x0;
    x0 += x1; x1 = rotl32(x1, 15); x1 ^= x0;
    x0 += x1; x1 = rotl32(x1, 26); x1 ^= x0;
    x0 += x1; x1 = rotl32(x1,  6); x1 ^= x0;
    x0 += ks1; x1 += ks2 + 1u;
    x0 += x1; x1 = rotl32(x1, 17); x1 ^= x0;
    x0 += x1; x1 = rotl32(x1, 29); x1 ^= x0;
    x0 += x1; x1 = rotl32(x1, 16); x1 ^= x0;
    x0 += x1; x1 = rotl32(x1, 24); x1 ^= x0;
    x0 += ks2; x1 += 0u + 2u;
    x0 += x1; x1 = rotl32(x1, 13); x1 ^= x0;
    x0 += x1; x1 = rotl32(x1, 15); x1 ^= x0;
    x0 += x1; x1 = rotl32(x1, 26); x1 ^= x0;
    x0 += x1; x1 = rotl32(x1,  6); x1 ^= x0;
    x0 += 0u; x1 += ks1 + 3u;
    x0 += x1; x1 = rotl32(x1, 17); x1 ^= x0;
    x0 += x1; x1 = rotl32(x1, 29); x1 ^= x0;
    x0 += x1; x1 = rotl32(x1, 16); x1 ^= x0;
    x0 += x1; x1 = rotl32(x1, 24); x1 ^= x0;
    x0 += ks1; x1 += ks2 + 4u;
    x0 += x1; x1 = rotl32(x1, 13); x1 ^= x0;
    x0 += x1; x1 = rotl32(x1, 15); x1 ^= x0;
    x0 += x1; x1 = rotl32(x1, 26); x1 ^= x0;
    x0 += x1; x1 = rotl32(x1,  6); x1 ^= x0;
    x0 += ks2; x1 += 0u + 5u;
    return make_uint2(x0, x1);
}

DEV_INLINE bool masked_at(uint32_t fi) {
    uint2 r = threefry2x32_k42(0u, fi);
    uint32_t bits = r.x ^ r.y;
    float u = __uint_as_float(0x3f800000u | (bits >> 9)) - 1.0f;
    return u < 0.3f;
}

// ===========================================================================
// Fused attention (unchanged, known-good). grid=(16,64), 256 thr.
// ===========================================================================
__global__ __launch_bounds__(256, 2) void attn_kernel()
{
    extern __shared__ float sm[];
    float* Qt   = sm;                 // [96][68]
    float* Kt   = Qt + 96 * 68;       // [96][68]
    float* Vs   = Kt + 96 * 68;       // [64][96]
    float* Ps   = Vs + 64 * 96;       // [64][68]
    float* redm = Ps + 64 * 68;       // [16][64]
    float* redz = redm + 1024;        // [16][64]
    float* m1s  = redz + 1024;
    float* z1s  = m1s + 64;
    float* m2s  = z1s + 64;
    float* z2s  = m2s + 64;
    float* zfs  = z2s + 64;

    const int qt = blockIdx.x, bh = blockIdx.y;
    const int b = bh >> 3, h = bh & 7;
    const int tid = threadIdx.x;
    const int tx = tid & 15, ty = tid >> 4;

    {
        const float* qg = g_q + ((size_t)(b * NtQ + qt * 64)) * Dm + h * HD;
        for (int t = tid; t < 64 * 24; t += 256) {
            int r = t / 24, c4 = t % 24;
            float4 v = *reinterpret_cast<const float4*>(qg + (size_t)r * Dm + c4 * 4);
            Qt[(c4 * 4 + 0) * 68 + r] = v.x * QSCALE;
            Qt[(c4 * 4 + 1) * 68 + r] = v.y * QSCALE;
            Qt[(c4 * 4 + 2) * 68 + r] = v.z * QSCALE;
            Qt[(c4 * 4 + 3) * 68 + r] = v.w * QSCALE;
        }
    }

    float m1p[4], z1p[4], m2p[4], z2p[4];
#pragma unroll
    for (int i = 0; i < 4; i++) { m1p[i] = -1e30f; z1p[i] = 0.f; m2p[i] = -1e30f; z2p[i] = 0.f; }

    float* sg = g_s + ((size_t)(bh * 1024 + qt * 64)) * 1024;

    // ---- PASS A ----
    for (int c = 0; c < 16; c++) {
        __syncthreads();
        const float* kg = g_kv + ((size_t)(b * Nk + c * 64)) * (2 * Dm) + h * HD;
        for (int t = tid; t < 64 * 24; t += 256) {
            int r = t / 24, c4 = t % 24;
            float4 v = *reinterpret_cast<const float4*>(kg + (size_t)r * (2 * Dm) + c4 * 4);
            Kt[(c4 * 4 + 0) * 68 + r] = v.x;
            Kt[(c4 * 4 + 1) * 68 + r] = v.y;
            Kt[(c4 * 4 + 2) * 68 + r] = v.z;
            Kt[(c4 * 4 + 3) * 68 + r] = v.w;
        }
        __syncthreads();

        float s[4][4];
#pragma unroll
        for (int i = 0; i < 4; i++)
#pragma unroll
            for (int j = 0; j < 4; j++) s[i][j] = 0.f;

#pragma unroll 8
        for (int kk = 0; kk < 96; kk++) {
            float4 qv = *reinterpret_cast<const float4*>(&Qt[kk * 68 + ty * 4]);
            float4 kv = *reinterpret_cast<const float4*>(&Kt[kk * 68 + tx * 4]);
            float qa[4] = {qv.x, qv.y, qv.z, qv.w};
            float ka[4] = {kv.x, kv.y, kv.z, kv.w};
#pragma unroll
            for (int i = 0; i < 4; i++)
#pragma unroll
                for (int j = 0; j < 4; j++) s[i][j] += qa[i] * ka[j];
        }

#pragma unroll
        for (int i = 0; i < 4; i++) {
            *reinterpret_cast<float4*>(sg + (size_t)(ty * 4 + i) * 1024 + c * 64 + tx * 4) =
                make_float4(s[i][0], s[i][1], s[i][2], s[i][3]);
        }

        const bool clsth = (c == 0 && tx < 5);
#pragma unroll
        for (int i = 0; i < 4; i++) {
            float lm = fmaxf(fmaxf(s[i][0], s[i][1]), fmaxf(s[i][2], s[i][3]));
            if (clsth) {
                float nm = fmaxf(m1p[i], lm);
                z1p[i] = z1p[i] * expf(m1p[i] - nm)
                       + expf(s[i][0] - nm) + expf(s[i][1] - nm)
                       + expf(s[i][2] - nm) + expf(s[i][3] - nm);
                m1p[i] = nm;
            } else {
                float nm = fmaxf(m2p[i], lm);
                z2p[i] = z2p[i] * expf(m2p[i] - nm)
                       + expf(s[i][0] - nm) + expf(s[i][1] - nm)
                       + expf(s[i][2] - nm) + expf(s[i][3] - nm);
                m2p[i] = nm;
            }
        }
    }

    __syncthreads();
#pragma unroll
    for (int i = 0; i < 4; i++) { redm[tx * 64 + ty * 4 + i] = m2p[i]; redz[tx * 64 + ty * 4 + i] = z2p[i]; }
    __syncthreads();
    if (tid < 64) {
        float m = -1e30f;
        for (int t = 0; t < 16; t++) m = fmaxf(m, redm[t * 64 + tid]);
        float z = 0.f;
        for (int t = 0; t < 16; t++) z += redz[t * 64 + tid] * expf(redm[t * 64 + tid] - m);
        m2s[tid] = m; z2s[tid] = z;
    }
    __syncthreads();
#pragma unroll
    for (int i = 0; i < 4; i++) {
        bool v = (tx < 5);
        redm[tx * 64 + ty * 4 + i] = v ? m1p[i] : -1e30f;
        redz[tx * 64 + ty * 4 + i] = v ? z1p[i] : 0.f;
    }
    __syncthreads();
    if (tid < 64) {
        float m = -1e30f;
        for (int t = 0; t < 16; t++) m = fmaxf(m, redm[t * 64 + tid]);
        float z = 0.f;
        for (int t = 0; t < 16; t++) z += redz[t * 64 + tid] * expf(redm[t * 64 + tid] - m);
        m1s[tid] = m; z1s[tid] = z;
    }

    // ---- PASS B ----
    float acc[4][6];
#pragma unroll
    for (int i = 0; i < 4; i++)
#pragma unroll
        for (int j = 0; j < 6; j++) acc[i][j] = 0.f;
    float zfp[4] = {0.f, 0.f, 0.f, 0.f};

    for (int c = 0; c < 16; c++) {
        __syncthreads();
        const float* vg = g_kv + ((size_t)(b * Nk + c * 64)) * (2 * Dm) + Dm + h * HD;
        for (int t = tid; t < 64 * 24; t += 256) {
            int r = t / 24, c4 = t % 24;
            *reinterpret_cast<float4*>(&Vs[r * 96 + c4 * 4]) =
                *reinterpret_cast<const float4*>(vg + (size_t)r * (2 * Dm) + c4 * 4);
        }

#pragma unroll
        for (int i = 0; i < 4; i++) {
            const int r = ty * 4 + i;
            const uint32_t l = 20u + (uint32_t)(qt * 64 + r);
            float4 sv = *reinterpret_cast<const float4*>(sg + (size_t)r * 1024 + c * 64 + tx * 4);
            float sa[4] = {sv.x, sv.y, sv.z, sv.w};
            const float m1 = m1s[r], z1 = z1s[r], m2 = m2s[r], z2 = z2s[r];
            float e[4];
#pragma unroll
            for (int j = 0; j < 4; j++) {
                const uint32_t n = (uint32_t)(c * 64 + tx * 4 + j);
                const bool iscls = (n < 20u);
                const float a = expf(sa[j] - (iscls ? m1 : m2)) / (iscls ? z1 : z2);
                const uint32_t fi = ((uint32_t)bh * 1044u + l) * 1024u + n;
                e[j] = masked_at(fi) ? 0.0f : expf(a - 1.0f);
                zfp[i] += e[j];
            }
            *reinterpret_cast<float4*>(&Ps[r * 68 + tx * 4]) = make_float4(e[0], e[1], e[2], e[3]);
        }
        __syncthreads();

#pragma unroll 2
        for (int n = 0; n < 64; n++) {
            float p0 = Ps[(ty * 4 + 0) * 68 + n];
            float p1 = Ps[(ty * 4 + 1) * 68 + n];
            float p2 = Ps[(ty * 4 + 2) * 68 + n];
            float p3 = Ps[(ty * 4 + 3) * 68 + n];
#pragma unroll
            for (int j = 0; j < 6; j++) {
                float vv = Vs[n * 96 + tx * 6 + j];
                acc[0][j] += p0 * vv;
                acc[1][j] += p1 * vv;
                acc[2][j] += p2 * vv;
                acc[3][j] += p3 * vv;
            }
        }
    }

    __syncthreads();
#pragma unroll
    for (int i = 0; i < 4; i++) redz[tx * 64 + ty * 4 + i] = zfp[i];
    __syncthreads();
    if (tid < 64) {
        float z = 0.f;
        for (int t = 0; t < 16; t++) z += redz[t * 64 + tid];
        zfs[tid] = z;
    }
    __syncthreads();

    float* og = g_ao + ((size_t)(b * NtQ + qt * 64)) * Dm + h * HD;
#pragma unroll
    for (int i = 0; i < 4; i++) {
        const float rz = 1.0f / zfs[ty * 4 + i];
#pragma unroll
        for (int j = 0; j < 6; j++)
            og[(size_t)(ty * 4 + i) * Dm + tx * 6 + j] = acc[i][j] * rz;
    }
}

// ---------------------------------------------------------------------------
extern "C" void kernel_launch(void* const* d_in, const int* in_sizes, int n_in,
                              void* d_out, int out_size)
{
    const float* input_query = (const float*)d_in[0];
    const float* input_key   = (const float*)d_in[1];
    const float* Wq          = (const float*)d_in[2];
    const float* Wkv         = (const float*)d_in[3];
    // d_in[4] = Wcls  -- provably unused (cls query rows are sliced away)
    const float* Wproj       = (const float*)d_in[5];
    const float* bproj       = (const float*)d_in[6];
    float* out = (float*)d_out;

    float *qp, *kvp, *aop;
    cudaGetSymbolAddress((void**)&qp,  g_q);
    cudaGetSymbolAddress((void**)&kvp, g_kv);
    cudaGetSymbolAddress((void**)&aop, g_ao);

    const int attn_smem = (96 * 68 * 2 + 64 * 96 + 64 * 68 + 1024 * 2 + 5 * 64) * 4;
    cudaFuncSetAttribute(attn_kernel, cudaFuncAttributeMaxDynamicSharedMemorySize, attn_smem);

    // q = input_query @ Wq          [8192,768]
    mma_gemm<false><<<dim3(6, 64), 256>>>(input_query, Wq, nullptr, qp, 8192, 768, 768);
    // kv = input_key @ Wkv          [8192,1536]
    mma_gemm<false><<<dim3(12, 64), 256>>>(input_key, Wkv, nullptr, kvp, 8192, 1536, 768);
    // fused double-softmax attention
    attn_kernel<<<dim3(16, 64), 256, attn_smem>>>();
    // out = attn_out @ Wproj + b    [8192,768]
    mma_gemm<true><<<dim3(6, 64), 256>>>(aop, Wproj, bproj, out, 8192, 768, 768);
}

// round 5
// speedup vs baseline: 2.2191x; 1.6523x over previous
#include <cuda_runtime.h>
#include <cuda_bf16.h>
#include <cstdint>

// ---------------------------------------------------------------------------
// CrossAttention: B=8, Nt=1024, N=1024, D=768, H=8, HD=96, CLS=20, L=1044
// Everything heavy on mma.sync bf16 hi/lo split (3-term). No tcgen05 (harness
// targets plain sm_103). Attention: S C-frag == P A-frag register fusion.
// ---------------------------------------------------------------------------

#define DEV_INLINE __device__ __forceinline__

constexpr int   Bsz  = 8;
constexpr int   NtQ  = 1024;
constexpr int   Dm   = 768;
constexpr float QSCALE = 0.10206207261596577f;   // 96^-0.5

// ---------------- scratch (static device globals; no allocation) -----------
__device__ float    g_q  [Bsz * NtQ * Dm];          // 25 MB (Wq out, fp32)
__device__ float    g_kv [Bsz * NtQ * 2 * Dm];      // 50 MB (Wkv out, fp32)
__device__ float    g_ao [Bsz * NtQ * Dm];          // 25 MB (attn out, fp32)
// prepared operands (bf16 hi/lo words), head-major
__device__ uint32_t g_qh [64 * 1024 * 48];          // 12.6 MB each
__device__ uint32_t g_ql [64 * 1024 * 48];
__device__ uint32_t g_kh [64 * 1024 * 48];
__device__ uint32_t g_kl [64 * 1024 * 48];
__device__ uint32_t g_vth[64 * 96 * 512];           // V transposed [bh][d][keypair]
__device__ uint32_t g_vtl[64 * 96 * 512];

// ---------------------------------------------------------------------------
// shared helpers
// ---------------------------------------------------------------------------
DEV_INLINE void split2(float x, float y, uint32_t& hi, uint32_t& lo) {
    __nv_bfloat162 h = __floats2bfloat162_rn(x, y);
    float hx = __bfloat162float(h.x), hy = __bfloat162float(h.y);
    __nv_bfloat162 l = __floats2bfloat162_rn(x - hx, y - hy);
    hi = *reinterpret_cast<uint32_t*>(&h);
    lo = *reinterpret_cast<uint32_t*>(&l);
}

DEV_INLINE void mma16816(float* d, const uint32_t* a, const uint32_t* b) {
    asm volatile(
        "mma.sync.aligned.m16n8k16.row.col.f32.bf16.bf16.f32 "
        "{%0,%1,%2,%3}, {%4,%5,%6,%7}, {%8,%9}, {%0,%1,%2,%3};"
        : "+f"(d[0]), "+f"(d[1]), "+f"(d[2]), "+f"(d[3])
        : "r"(a[0]), "r"(a[1]), "r"(a[2]), "r"(a[3]), "r"(b[0]), "r"(b[1]));
}

DEV_INLINE uint32_t rotl32(uint32_t x, int d) { return __funnelshift_l(x, x, d); }

// JAX threefry2x32, key (0,42), partitionable stream: counter (0, fi), out = x0^x1
DEV_INLINE uint32_t tf_bits(uint32_t fi) {
    const uint32_t ks1 = 42u, ks2 = 0x1BD11BF0u;
    uint32_t x0 = 0u, x1 = fi + ks1;
    x0 += x1; x1 = rotl32(x1, 13); x1 ^= x0;
    x0 += x1; x1 = rotl32(x1, 15); x1 ^= x0;
    x0 += x1; x1 = rotl32(x1, 26); x1 ^= x0;
    x0 += x1; x1 = rotl32(x1,  6); x1 ^= x0;
    x0 += ks1; x1 += ks2 + 1u;
    x0 += x1; x1 = rotl32(x1, 17); x1 ^= x0;
    x0 += x1; x1 = rotl32(x1, 29); x1 ^= x0;
    x0 += x1; x1 = rotl32(x1, 16); x1 ^= x0;
    x0 += x1; x1 = rotl32(x1, 24); x1 ^= x0;
    x0 += ks2; x1 += 2u;
    x0 += x1; x1 = rotl32(x1, 13); x1 ^= x0;
    x0 += x1; x1 = rotl32(x1, 15); x1 ^= x0;
    x0 += x1; x1 = rotl32(x1, 26); x1 ^= x0;
    x0 += x1; x1 = rotl32(x1,  6); x1 ^= x0;
    x1 += ks1 + 3u;
    x0 += x1; x1 = rotl32(x1, 17); x1 ^= x0;
    x0 += x1; x1 = rotl32(x1, 29); x1 ^= x0;
    x0 += x1; x1 = rotl32(x1, 16); x1 ^= x0;
    x0 += x1; x1 = rotl32(x1, 24); x1 ^= x0;
    x0 += ks1; x1 += ks2 + 4u;
    x0 += x1; x1 = rotl32(x1, 13); x1 ^= x0;
    x0 += x1; x1 = rotl32(x1, 15); x1 ^= x0;
    x0 += x1; x1 = rotl32(x1, 26); x1 ^= x0;
    x0 += x1; x1 = rotl32(x1,  6); x1 ^= x0;
    x0 += ks2; x1 += 5u;
    return x0 ^ x1;
}
// keep (not masked)  <=>  bits>>9 >= 2516583   ( <=> u >= 0.3f exactly )

// ===========================================================================
//  mma.sync GEMM (validated round 4): C = A@B (+bias)
// ===========================================================================
constexpr int SSTR = 20;

template<bool BIAS>
__global__ __launch_bounds__(256, 2) void mma_gemm(
    const float* __restrict__ A, const float* __restrict__ Bm,
    const float* __restrict__ bias, float* __restrict__ C,
    int M, int N, int K)
{
    __shared__ uint32_t Ah[128 * SSTR];
    __shared__ uint32_t Al[128 * SSTR];
    __shared__ uint32_t Bh[128 * SSTR];
    __shared__ uint32_t Bl[128 * SSTR];

    const int tid  = threadIdx.x;
    const int lane = tid & 31;
    const int wid  = tid >> 5;
    const int wy   = wid >> 2;
    const int wx   = wid & 3;

    const int m0 = blockIdx.y * 128;
    const int n0 = blockIdx.x * 128;

    float acc[4][4][4];
#pragma unroll
    for (int i = 0; i < 4; i++)
#pragma unroll
        for (int j = 0; j < 4; j++)
#pragma unroll
            for (int q = 0; q < 4; q++) acc[i][j][q] = 0.f;

    const int gq = lane >> 2;
    const int gt = lane & 3;

    for (int kc = 0; kc < K; kc += 32) {
        __syncthreads();
#pragma unroll
        for (int p = 0; p < 4; p++) {
            const int idx = tid + p * 256;
            const int row = idx >> 3, c4 = idx & 7;
            float4 v = *reinterpret_cast<const float4*>(
                A + (size_t)(m0 + row) * K + kc + c4 * 4);
            uint32_t h01, l01, h23, l23;
            split2(v.x, v.y, h01, l01);
            split2(v.z, v.w, h23, l23);
            const int w = row * SSTR + c4 * 2;
            Ah[w] = h01; Ah[w + 1] = h23;
            Al[w] = l01; Al[w + 1] = l23;
        }
        {
            const int n  = tid & 127;
            const int kq = tid >> 7;
            const float* Bg = Bm + (size_t)kc * N + n0 + n;
#pragma unroll
            for (int p = 0; p < 8; p++) {
                const int k = kq * 16 + p * 2;
                float x = Bg[(size_t)k * N];
                float y = Bg[(size_t)(k + 1) * N];
                uint32_t h, l;
                split2(x, y, h, l);
                const int w = n * SSTR + k / 2;
                Bh[w] = h; Bl[w] = l;
            }
        }
        __syncthreads();

#pragma unroll
        for (int ks = 0; ks < 2; ks++) {
            uint32_t ah[4][4], al[4][4];
#pragma unroll
            for (int mt = 0; mt < 4; mt++) {
                const int r  = wy * 64 + mt * 16 + gq;
                const int cw = ks * 8 + gt;
                ah[mt][0] = Ah[r * SSTR + cw];
                ah[mt][1] = Ah[(r + 8) * SSTR + cw];
                ah[mt][2] = Ah[r * SSTR + cw + 4];
                ah[mt][3] = Ah[(r + 8) * SSTR + cw + 4];
                al[mt][0] = Al[r * SSTR + cw];
                al[mt][1] = Al[(r + 8) * SSTR + cw];
                al[mt][2] = Al[r * SSTR + cw + 4];
                al[mt][3] = Al[(r + 8) * SSTR + cw + 4];
            }
#pragma unroll
            for (int nt = 0; nt < 4; nt++) {
                const int n  = wx * 32 + nt * 8 + gq;
                const int kw = ks * 8 + gt;
                uint32_t bh[2], bl[2];
                bh[0] = Bh[n * SSTR + kw];
                bh[1] = Bh[n * SSTR + kw + 4];
                bl[0] = Bl[n * SSTR + kw];
                bl[1] = Bl[n * SSTR + kw + 4];
#pragma unroll
                for (int mt = 0; mt < 4; mt++) {
                    mma16816(acc[mt][nt], ah[mt], bh);
                    mma16816(acc[mt][nt], ah[mt], bl);
                    mma16816(acc[mt][nt], al[mt], bh);
                }
            }
        }
    }

#pragma unroll
    for (int mt = 0; mt < 4; mt++) {
        const int r0 = m0 + wy * 64 + mt * 16 + gq;
#pragma unroll
        for (int nt = 0; nt < 4; nt++) {
            const int col = n0 + wx * 32 + nt * 8 + gt * 2;
            float bx = 0.f, by = 0.f;
            if (BIAS) { bx = bias[col]; by = bias[col + 1]; }
            *reinterpret_cast<float2*>(C + (size_t)r0 * N + col) =
                make_float2(acc[mt][nt][0] + bx, acc[mt][nt][1] + by);
            *reinterpret_cast<float2*>(C + (size_t)(r0 + 8) * N + col) =
                make_float2(acc[mt][nt][2] + bx, acc[mt][nt][3] + by);
        }
    }
}

// ===========================================================================
//  prep: split Q (scaled) / K into bf16 hi/lo head-major; transpose+split V
//  grid (16 ntiles, 64 bh), 256 threads
// ===========================================================================
__global__ __launch_bounds__(256) void prep_kernel()
{
    __shared__ float vs[64 * 100];
    const int nt = blockIdx.x, bh = blockIdx.y;
    const int b = bh >> 3, h = bh & 7;
    const int tid = threadIdx.x;
    const int n0 = nt * 64;

#pragma unroll
    for (int p = 0; p < 6; p++) {
        const int idx = tid + p * 256;
        const int row = idx / 24, c4 = idx % 24;
        const size_t grow = (size_t)(b * 1024 + n0 + row);
        // Q (scaled)
        float4 qv = *reinterpret_cast<const float4*>(g_q + grow * 768 + h * 96 + c4 * 4);
        uint32_t h01, l01, h23, l23;
        split2(qv.x * QSCALE, qv.y * QSCALE, h01, l01);
        split2(qv.z * QSCALE, qv.w * QSCALE, h23, l23);
        const size_t w = (size_t)(bh * 1024 + n0 + row) * 48 + c4 * 2;
        *reinterpret_cast<uint2*>(g_qh + w) = make_uint2(h01, h23);
        *reinterpret_cast<uint2*>(g_ql + w) = make_uint2(l01, l23);
        // K
        const float* kg = g_kv + grow * 1536 + h * 96 + c4 * 4;
        float4 kv = *reinterpret_cast<const float4*>(kg);
        split2(kv.x, kv.y, h01, l01);
        split2(kv.z, kv.w, h23, l23);
        *reinterpret_cast<uint2*>(g_kh + w) = make_uint2(h01, h23);
        *reinterpret_cast<uint2*>(g_kl + w) = make_uint2(l01, l23);
        // V -> smem stage
        float4 vv = *reinterpret_cast<const float4*>(kg + 768);
        *reinterpret_cast<float4*>(&vs[row * 100 + c4 * 4]) = vv;
    }
    __syncthreads();
    // transpose: out word (d, key-pair)
#pragma unroll
    for (int p = 0; p < 12; p++) {
        const int idx = tid + p * 256;      // 3072 words
        const int d = idx >> 5, nw = idx & 31;
        float v0 = vs[(2 * nw) * 100 + d];
        float v1 = vs[(2 * nw + 1) * 100 + d];
        uint32_t hh, ll;
        split2(v0, v1, hh, ll);
        const size_t w = (size_t)(bh * 96 + d) * 512 + nt * 32 + nw;
        g_vth[w] = hh; g_vtl[w] = ll;
    }
}

// ===========================================================================
//  fused attention on mma.sync. grid (8 qtiles of 128, 64 bh), 256 thr.
// ===========================================================================
// smem strides (uint32 words per row)
constexpr int QSTR = 52;   // Q/K rows: 48 words + pad (conflict-free)
constexpr int VSTR = 36;   // V rows: 32 words + pad

DEV_INLINE void qk_mma(const uint32_t* Qh, const uint32_t* Ql,
                       const uint32_t* Kh, const uint32_t* Kl,
                       int rowb, int gq, int gt, float (*sacc)[4])
{
#pragma unroll
    for (int i = 0; i < 8; i++)
#pragma unroll
        for (int j = 0; j < 4; j++) sacc[i][j] = 0.f;
#pragma unroll
    for (int ks = 0; ks < 6; ks++) {
        const int cw = ks * 8 + gt;
        const int ra = (rowb + gq) * QSTR + cw;
        uint32_t ah[4], al[4];
        ah[0] = Qh[ra];            ah[1] = Qh[ra + 8 * QSTR];
        ah[2] = Qh[ra + 4];        ah[3] = Qh[ra + 8 * QSTR + 4];
        al[0] = Ql[ra];            al[1] = Ql[ra + 8 * QSTR];
        al[2] = Ql[ra + 4];        al[3] = Ql[ra + 8 * QSTR + 4];
#pragma unroll
        for (int nt = 0; nt < 8; nt++) {
            const int nb = (nt * 8 + gq) * QSTR + cw;
            uint32_t bh2[2] = {Kh[nb], Kh[nb + 4]};
            uint32_t bl2[2] = {Kl[nb], Kl[nb + 4]};
            mma16816(sacc[nt], ah, bh2);
            mma16816(sacc[nt], ah, bl2);
            mma16816(sacc[nt], al, bh2);
        }
    }
}

DEV_INLINE void online_upd(float& m, float& z, float s) {
    float nm = fmaxf(m, s);
    z = z * __expf(m - nm) + __expf(s - nm);
    m = nm;
}
DEV_INLINE void comb_mz(float& m, float& z, int d) {
    float mo = __shfl_xor_sync(0xffffffffu, m, d);
    float zo = __shfl_xor_sync(0xffffffffu, z, d);
    float nm = fmaxf(m, mo);
    z = z * __expf(m - nm) + zo * __expf(mo - nm);
    m = nm;
}

__global__ __launch_bounds__(256, 2) void attn_mma()
{
    extern __shared__ uint32_t smw[];
    uint32_t* Qh = smw;                  // 128*52 = 6656
    uint32_t* Ql = Qh + 128 * QSTR;
    uint32_t* Kh = Ql + 128 * QSTR;      // 64*52 = 3328
    uint32_t* Kl = Kh + 64 * QSTR;
    uint32_t* Vh = Kl + 64 * QSTR;       // 96*36 = 3456
    uint32_t* Vl = Vh + 96 * VSTR;

    const int qt = blockIdx.x, bh = blockIdx.y;
    const int b = bh >> 3, h = bh & 7;
    const int tid = threadIdx.x, lane = tid & 31, wid = tid >> 5;
    const int gq = lane >> 2, gt = lane & 3;
    const int rowb = wid * 16;

    // ---- load Q tile (pre-split) ----
    {
        const uint4* qh4 = reinterpret_cast<const uint4*>(g_qh + (size_t)(bh * 1024 + qt * 128) * 48);
        const uint4* ql4 = reinterpret_cast<const uint4*>(g_ql + (size_t)(bh * 1024 + qt * 128) * 48);
#pragma unroll
        for (int p = 0; p < 6; p++) {
            const int idx = tid + p * 256;
            const int row = idx / 12, s = idx % 12;
            *reinterpret_cast<uint4*>(&Qh[row * QSTR + s * 4]) = qh4[row * 12 + s];
            *reinterpret_cast<uint4*>(&Ql[row * QSTR + s * 4]) = ql4[row * 12 + s];
        }
    }

    float m1[2] = {-1e30f, -1e30f}, z1[2] = {0.f, 0.f};
    float m2[2] = {-1e30f, -1e30f}, z2[2] = {0.f, 0.f};
    float sacc[8][4];

    // ================= PASS A: stats =================
    for (int c = 0; c < 16; c++) {
        __syncthreads();
        {
            const uint4* kh4 = reinterpret_cast<const uint4*>(g_kh + (size_t)(bh * 1024 + c * 64) * 48);
            const uint4* kl4 = reinterpret_cast<const uint4*>(g_kl + (size_t)(bh * 1024 + c * 64) * 48);
#pragma unroll
            for (int p = 0; p < 3; p++) {
                const int idx = tid + p * 256;
                const int row = idx / 12, s = idx % 12;
                *reinterpret_cast<uint4*>(&Kh[row * QSTR + s * 4]) = kh4[row * 12 + s];
                *reinterpret_cast<uint4*>(&Kl[row * QSTR + s * 4]) = kl4[row * 12 + s];
            }
        }
        __syncthreads();
        qk_mma(Qh, Ql, Kh, Kl, rowb, gq, gt, sacc);

        if (c == 0) {
#pragma unroll
            for (int nt = 0; nt < 8; nt++)
#pragma unroll
                for (int v = 0; v < 4; v++) {
                    const int col = nt * 8 + gt * 2 + (v & 1);
                    const int r = v >> 1;
                    if (col < 20) online_upd(m1[r], z1[r], sacc[nt][v]);
                    else          online_upd(m2[r], z2[r], sacc[nt][v]);
                }
        } else {
#pragma unroll
            for (int r = 0; r < 2; r++) {
                float lm = -1e30f;
#pragma unroll
                for (int nt = 0; nt < 8; nt++)
                    lm = fmaxf(lm, fmaxf(sacc[nt][r * 2], sacc[nt][r * 2 + 1]));
                const float nm = fmaxf(m2[r], lm);
                float zs = 0.f;
#pragma unroll
                for (int nt = 0; nt < 8; nt++)
                    zs += __expf(sacc[nt][r * 2] - nm) + __expf(sacc[nt][r * 2 + 1] - nm);
                z2[r] = z2[r] * __expf(m2[r] - nm) + zs;
                m2[r] = nm;
            }
        }
    }
    // quad reduce (lanes gt 0..3 hold the full rows afterwards)
#pragma unroll
    for (int r = 0; r < 2; r++) {
        comb_mz(m1[r], z1[r], 1); comb_mz(m1[r], z1[r], 2);
        comb_mz(m2[r], z2[r], 1); comb_mz(m2[r], z2[r], 2);
    }
    const float rz1[2] = {1.f / z1[0], 1.f / z1[1]};
    const float rz2[2] = {1.f / z2[0], 1.f / z2[1]};

    // ================= PASS B =================
    float vacc[12][4];
#pragma unroll
    for (int i = 0; i < 12; i++)
#pragma unroll
        for (int j = 0; j < 4; j++) vacc[i][j] = 0.f;
    float zf[2] = {0.f, 0.f};
    const uint32_t l0 = 20u + (uint32_t)(qt * 128 + rowb + gq);

    for (int c = 0; c < 16; c++) {
        __syncthreads();
        {
            const uint4* kh4 = reinterpret_cast<const uint4*>(g_kh + (size_t)(bh * 1024 + c * 64) * 48);
            const uint4* kl4 = reinterpret_cast<const uint4*>(g_kl + (size_t)(bh * 1024 + c * 64) * 48);
#pragma unroll
            for (int p = 0; p < 3; p++) {
                const int idx = tid + p * 256;
                const int row = idx / 12, s = idx % 12;
                *reinterpret_cast<uint4*>(&Kh[row * QSTR + s * 4]) = kh4[row * 12 + s];
                *reinterpret_cast<uint4*>(&Kl[row * QSTR + s * 4]) = kl4[row * 12 + s];
            }
            const uint4* vh4 = reinterpret_cast<const uint4*>(g_vth + (size_t)(bh * 96) * 512);
            const uint4* vl4 = reinterpret_cast<const uint4*>(g_vtl + (size_t)(bh * 96) * 512);
#pragma unroll
            for (int p = 0; p < 3; p++) {
                const int idx = tid + p * 256;   // 768 = 96 rows * 8
                const int row = idx >> 3, s = idx & 7;
                *reinterpret_cast<uint4*>(&Vh[row * VSTR + s * 4]) = vh4[row * 128 + c * 8 + s];
                *reinterpret_cast<uint4*>(&Vl[row * VSTR + s * 4]) = vl4[row * 128 + c * 8 + s];
            }
        }
        __syncthreads();
        qk_mma(Qh, Ql, Kh, Kl, rowb, gq, gt, sacc);

        // P in registers + PV, interleaved per k16 step
#pragma unroll
        for (int ks = 0; ks < 4; ks++) {
            uint32_t pah[4], pal[4];
#pragma unroll
            for (int half = 0; half < 2; half++) {
                const int nt = 2 * ks + half;
                float e[4];
#pragma unroll
                for (int v = 0; v < 4; v++) {
                    const int col = c * 64 + nt * 8 + gt * 2 + (v & 1);
                    const int r = v >> 1;
                    const bool cls = col < 20;
                    const float m  = cls ? m1[r] : m2[r];
                    const float rz = cls ? rz1[r] : rz2[r];
                    const float a  = __expf(sacc[nt][v] - m) * rz;
                    const uint32_t l  = l0 + (uint32_t)(r * 8);
                    const uint32_t fi = ((uint32_t)bh * 1044u + l) * 1024u + (uint32_t)col;
                    const uint32_t bits = tf_bits(fi);
                    const float ev = ((bits >> 9) >= 2516583u) ? __expf(a - 1.f) : 0.f;
                    e[v] = ev;
                    zf[r] += ev;
                }
                uint32_t hh, ll;
                split2(e[0], e[1], hh, ll);
                pah[half * 2] = hh;     pal[half * 2] = ll;
                split2(e[2], e[3], hh, ll);
                pah[half * 2 + 1] = hh; pal[half * 2 + 1] = ll;
            }
            const int kw = ks * 8 + gt;
#pragma unroll
            for (int nt = 0; nt < 12; nt++) {
                const int nb = (nt * 8 + gq) * VSTR + kw;
                uint32_t bh2[2] = {Vh[nb], Vh[nb + 4]};
                uint32_t bl2[2] = {Vl[nb], Vl[nb + 4]};
                mma16816(vacc[nt], pah, bh2);
                mma16816(vacc[nt], pah, bl2);
                mma16816(vacc[nt], pal, bh2);
            }
        }
    }

    // zf quad reduce + write out
#pragma unroll
    for (int r = 0; r < 2; r++) {
        zf[r] += __shfl_xor_sync(0xffffffffu, zf[r], 1);
        zf[r] += __shfl_xor_sync(0xffffffffu, zf[r], 2);
    }
    const float r0 = 1.f / zf[0], r1 = 1.f / zf[1];
    const int qrow = qt * 128 + rowb + gq;
    float* og = g_ao + (size_t)(b * 1024 + qrow) * 768 + h * 96;
#pragma unroll
    for (int nt = 0; nt < 12; nt++) {
        const int col = nt * 8 + gt * 2;
        *reinterpret_cast<float2*>(og + col) =
            make_float2(vacc[nt][0] * r0, vacc[nt][1] * r0);
        *reinterpret_cast<float2*>(og + 8 * 768 + col) =
            make_float2(vacc[nt][2] * r1, vacc[nt][3] * r1);
    }
}

// ---------------------------------------------------------------------------
extern "C" void kernel_launch(void* const* d_in, const int* in_sizes, int n_in,
                              void* d_out, int out_size)
{
    const float* input_query = (const float*)d_in[0];
    const float* input_key   = (const float*)d_in[1];
    const float* Wq          = (const float*)d_in[2];
    const float* Wkv         = (const float*)d_in[3];
    // d_in[4] = Wcls  -- provably unused (cls query rows are sliced away)
    const float* Wproj       = (const float*)d_in[5];
    const float* bproj       = (const float*)d_in[6];
    float* out = (float*)d_out;

    float *qp, *kvp, *aop;
    cudaGetSymbolAddress((void**)&qp,  g_q);
    cudaGetSymbolAddress((void**)&kvp, g_kv);
    cudaGetSymbolAddress((void**)&aop, g_ao);

    const int attn_smem = (128 * QSTR * 2 + 64 * QSTR * 2 + 96 * VSTR * 2) * 4; // 107520
    cudaFuncSetAttribute(attn_mma, cudaFuncAttributeMaxDynamicSharedMemorySize, attn_smem);

    // q = input_query @ Wq          [8192,768]
    mma_gemm<false><<<dim3(6, 64), 256>>>(input_query, Wq, nullptr, qp, 8192, 768, 768);
    // kv = input_key @ Wkv          [8192,1536]
    mma_gemm<false><<<dim3(12, 64), 256>>>(input_key, Wkv, nullptr, kvp, 8192, 1536, 768);
    // split/transpose prep
    prep_kernel<<<dim3(16, 64), 256>>>();
    // fused attention (mma.sync)
    attn_mma<<<dim3(8, 64), 256, attn_smem>>>();
    // out = attn_out @ Wproj + b    [8192,768]
    mma_gemm<true><<<dim3(6, 64), 256>>>(aop, Wproj, bproj, out, 8192, 768, 768);
}

// round 6
// speedup vs baseline: 2.3598x; 1.0634x over previous
#include <cuda_runtime.h>
#include <cuda_bf16.h>
#include <cstdint>

// ---------------------------------------------------------------------------
// CrossAttention: B=8, Nt=1024, N=1024, D=768, H=8, HD=96, CLS=20, L=1044
// mma.sync bf16 hi/lo split everywhere. Threefry mask precomputed as a bitmask
// inside the projection GEMMs (fills idle issue slots). Attention pass A is
// hi-only (stats precision argument in commit log).
// ---------------------------------------------------------------------------

#define DEV_INLINE __device__ __forceinline__

constexpr int   Bsz  = 8;
constexpr int   NtQ  = 1024;
constexpr int   Dm   = 768;
constexpr float QSCALE = 0.10206207261596577f;   // 96^-0.5

// ---------------- scratch (static device globals; no allocation) -----------
__device__ float    g_q  [Bsz * NtQ * Dm];          // 25 MB
__device__ float    g_kv [Bsz * NtQ * 2 * Dm];      // 50 MB
__device__ float    g_ao [Bsz * NtQ * Dm];          // 25 MB
__device__ uint32_t g_qh [64 * 1024 * 48];
__device__ uint32_t g_ql [64 * 1024 * 48];
__device__ uint32_t g_kh [64 * 1024 * 48];
__device__ uint32_t g_kl [64 * 1024 * 48];
__device__ uint32_t g_vth[64 * 96 * 512];
__device__ uint32_t g_vtl[64 * 96 * 512];
__device__ uint32_t g_mask[64 * 1024 * 32];         // 8.4 MB keep-bitmask

// ---------------------------------------------------------------------------
DEV_INLINE void split2(float x, float y, uint32_t& hi, uint32_t& lo) {
    __nv_bfloat162 h = __floats2bfloat162_rn(x, y);
    float hx = __bfloat162float(h.x), hy = __bfloat162float(h.y);
    __nv_bfloat162 l = __floats2bfloat162_rn(x - hx, y - hy);
    hi = *reinterpret_cast<uint32_t*>(&h);
    lo = *reinterpret_cast<uint32_t*>(&l);
}

DEV_INLINE void mma16816(float* d, const uint32_t* a, const uint32_t* b) {
    asm volatile(
        "mma.sync.aligned.m16n8k16.row.col.f32.bf16.bf16.f32 "
        "{%0,%1,%2,%3}, {%4,%5,%6,%7}, {%8,%9}, {%0,%1,%2,%3};"
        : "+f"(d[0]), "+f"(d[1]), "+f"(d[2]), "+f"(d[3])
        : "r"(a[0]), "r"(a[1]), "r"(a[2]), "r"(a[3]), "r"(b[0]), "r"(b[1]));
}

DEV_INLINE uint32_t rotl32(uint32_t x, int d) { return __funnelshift_l(x, x, d); }

// JAX threefry2x32, key (0,42), partitionable: counter (0, fi), out = x0^x1
DEV_INLINE uint32_t tf_bits(uint32_t fi) {
    const uint32_t ks1 = 42u, ks2 = 0x1BD11BF0u;
    uint32_t x0 = 0u, x1 = fi + ks1;
    x0 += x1; x1 = rotl32(x1, 13); x1 ^= x0;
    x0 += x1; x1 = rotl32(x1, 15); x1 ^= x0;
    x0 += x1; x1 = rotl32(x1, 26); x1 ^= x0;
    x0 += x1; x1 = rotl32(x1,  6); x1 ^= x0;
    x0 += ks1; x1 += ks2 + 1u;
    x0 += x1; x1 = rotl32(x1, 17); x1 ^= x0;
    x0 += x1; x1 = rotl32(x1, 29); x1 ^= x0;
    x0 += x1; x1 = rotl32(x1, 16); x1 ^= x0;
    x0 += x1; x1 = rotl32(x1, 24); x1 ^= x0;
    x0 += ks2; x1 += 2u;
    x0 += x1; x1 = rotl32(x1, 13); x1 ^= x0;
    x0 += x1; x1 = rotl32(x1, 15); x1 ^= x0;
    x0 += x1; x1 = rotl32(x1, 26); x1 ^= x0;
    x0 += x1; x1 = rotl32(x1,  6); x1 ^= x0;
    x1 += ks1 + 3u;
    x0 += x1; x1 = rotl32(x1, 17); x1 ^= x0;
    x0 += x1; x1 = rotl32(x1, 29); x1 ^= x0;
    x0 += x1; x1 = rotl32(x1, 16); x1 ^= x0;
    x0 += x1; x1 = rotl32(x1, 24); x1 ^= x0;
    x0 += ks1; x1 += ks2 + 4u;
    x0 += x1; x1 = rotl32(x1, 13); x1 ^= x0;
    x0 += x1; x1 = rotl32(x1, 15); x1 ^= x0;
    x0 += x1; x1 = rotl32(x1, 26); x1 ^= x0;
    x0 += x1; x1 = rotl32(x1,  6); x1 ^= x0;
    x0 += ks2; x1 += 5u;
    return x0 ^ x1;
}

// one 32-bit mask word: w = (bh*1024 + q)*32 + wi ; bit j -> col wi*32+j
// bit = 1 <=> KEEP  <=> (bits>>9) >= 2516583  ( <=> u >= 0.3f exactly )
DEV_INLINE uint32_t mask_word(uint32_t w) {
    const uint32_t bh = w >> 15;
    const uint32_t rest = w & 32767u;
    const uint32_t q = rest >> 5, wi = rest & 31u;
    const uint32_t fi0 = (bh * 1044u + 20u + q) * 1024u + wi * 32u;
    uint32_t bits = 0u;
#pragma unroll 4
    for (int j = 0; j < 32; j++) {
        uint32_t b = tf_bits(fi0 + (uint32_t)j);
        bits |= ((b >> 9) >= 2516583u ? 1u : 0u) << j;
    }
    return bits;
}

// ===========================================================================
//  mma.sync GEMM (round-4 validated) + fused mask-word generation
// ===========================================================================
constexpr int SSTR = 20;

template<bool BIAS>
__global__ __launch_bounds__(256, 2) void mma_gemm(
    const float* __restrict__ A, const float* __restrict__ Bm,
    const float* __restrict__ bias, float* __restrict__ C,
    int M, int N, int K,
    uint32_t mw_start, uint32_t mw_end, uint32_t mw_stride)
{
    __shared__ uint32_t Ah[128 * SSTR];
    __shared__ uint32_t Al[128 * SSTR];
    __shared__ uint32_t Bh[128 * SSTR];
    __shared__ uint32_t Bl[128 * SSTR];

    const int tid  = threadIdx.x;
    const int lane = tid & 31;
    const int wid  = tid >> 5;
    const int wy   = wid >> 2;
    const int wx   = wid & 3;

    const int m0 = blockIdx.y * 128;
    const int n0 = blockIdx.x * 128;
    const uint32_t gid =
        ((uint32_t)blockIdx.y * gridDim.x + blockIdx.x) * 256u + (uint32_t)tid;

    float acc[4][4][4];
#pragma unroll
    for (int i = 0; i < 4; i++)
#pragma unroll
        for (int j = 0; j < 4; j++)
#pragma unroll
            for (int q = 0; q < 4; q++) acc[i][j][q] = 0.f;

    const int gq = lane >> 2;
    const int gt = lane & 3;

    for (int kc = 0; kc < K; kc += 32) {
        __syncthreads();
#pragma unroll
        for (int p = 0; p < 4; p++) {
            const int idx = tid + p * 256;
            const int row = idx >> 3, c4 = idx & 7;
            float4 v = *reinterpret_cast<const float4*>(
                A + (size_t)(m0 + row) * K + kc + c4 * 4);
            uint32_t h01, l01, h23, l23;
            split2(v.x, v.y, h01, l01);
            split2(v.z, v.w, h23, l23);
            const int w = row * SSTR + c4 * 2;
            Ah[w] = h01; Ah[w + 1] = h23;
            Al[w] = l01; Al[w + 1] = l23;
        }
        {
            const int n  = tid & 127;
            const int kq = tid >> 7;
            const float* Bg = Bm + (size_t)kc * N + n0 + n;
#pragma unroll
            for (int p = 0; p < 8; p++) {
                const int k = kq * 16 + p * 2;
                float x = Bg[(size_t)k * N];
                float y = Bg[(size_t)(k + 1) * N];
                uint32_t h, l;
                split2(x, y, h, l);
                const int w = n * SSTR + k / 2;
                Bh[w] = h; Bl[w] = l;
            }
        }
        // ---- fused mask generation: 1 word/thread/iter (fills stall slots) ----
        if (mw_stride) {
            const uint32_t w = mw_start + gid + (uint32_t)(kc >> 5) * mw_stride;
            if (w < mw_end) g_mask[w] = mask_word(w);
        }
        __syncthreads();

#pragma unroll
        for (int ks = 0; ks < 2; ks++) {
            uint32_t ah[4][4], al[4][4];
#pragma unroll
            for (int mt = 0; mt < 4; mt++) {
                const int r  = wy * 64 + mt * 16 + gq;
                const int cw = ks * 8 + gt;
                ah[mt][0] = Ah[r * SSTR + cw];
                ah[mt][1] = Ah[(r + 8) * SSTR + cw];
                ah[mt][2] = Ah[r * SSTR + cw + 4];
                ah[mt][3] = Ah[(r + 8) * SSTR + cw + 4];
                al[mt][0] = Al[r * SSTR + cw];
                al[mt][1] = Al[(r + 8) * SSTR + cw];
                al[mt][2] = Al[r * SSTR + cw + 4];
                al[mt][3] = Al[(r + 8) * SSTR + cw + 4];
            }
#pragma unroll
            for (int nt = 0; nt < 4; nt++) {
                const int n  = wx * 32 + nt * 8 + gq;
                const int kw = ks * 8 + gt;
                uint32_t bh[2], bl[2];
                bh[0] = Bh[n * SSTR + kw];
                bh[1] = Bh[n * SSTR + kw + 4];
                bl[0] = Bl[n * SSTR + kw];
                bl[1] = Bl[n * SSTR + kw + 4];
#pragma unroll
                for (int mt = 0; mt < 4; mt++) {
                    mma16816(acc[mt][nt], ah[mt], bh);
                    mma16816(acc[mt][nt], ah[mt], bl);
                    mma16816(acc[mt][nt], al[mt], bh);
                }
            }
        }
    }

#pragma unroll
    for (int mt = 0; mt < 4; mt++) {
        const int r0 = m0 + wy * 64 + mt * 16 + gq;
#pragma unroll
        for (int nt = 0; nt < 4; nt++) {
            const int col = n0 + wx * 32 + nt * 8 + gt * 2;
            float bx = 0.f, by = 0.f;
            if (BIAS) { bx = bias[col]; by = bias[col + 1]; }
            *reinterpret_cast<float2*>(C + (size_t)r0 * N + col) =
                make_float2(acc[mt][nt][0] + bx, acc[mt][nt][1] + by);
            *reinterpret_cast<float2*>(C + (size_t)(r0 + 8) * N + col) =
                make_float2(acc[mt][nt][2] + bx, acc[mt][nt][3] + by);
        }
    }
}

// ===========================================================================
//  prep: split Q (scaled) / K head-major; transpose+split V
// ===========================================================================
__global__ __launch_bounds__(256) void prep_kernel()
{
    __shared__ float vs[64 * 100];
    const int nt = blockIdx.x, bh = blockIdx.y;
    const int b = bh >> 3, h = bh & 7;
    const int tid = threadIdx.x;
    const int n0 = nt * 64;

#pragma unroll
    for (int p = 0; p < 6; p++) {
        const int idx = tid + p * 256;
        const int row = idx / 24, c4 = idx % 24;
        const size_t grow = (size_t)(b * 1024 + n0 + row);
        float4 qv = *reinterpret_cast<const float4*>(g_q + grow * 768 + h * 96 + c4 * 4);
        uint32_t h01, l01, h23, l23;
        split2(qv.x * QSCALE, qv.y * QSCALE, h01, l01);
        split2(qv.z * QSCALE, qv.w * QSCALE, h23, l23);
        const size_t w = (size_t)(bh * 1024 + n0 + row) * 48 + c4 * 2;
        *reinterpret_cast<uint2*>(g_qh + w) = make_uint2(h01, h23);
        *reinterpret_cast<uint2*>(g_ql + w) = make_uint2(l01, l23);
        const float* kg = g_kv + grow * 1536 + h * 96 + c4 * 4;
        float4 kv = *reinterpret_cast<const float4*>(kg);
        split2(kv.x, kv.y, h01, l01);
        split2(kv.z, kv.w, h23, l23);
        *reinterpret_cast<uint2*>(g_kh + w) = make_uint2(h01, h23);
        *reinterpret_cast<uint2*>(g_kl + w) = make_uint2(l01, l23);
        float4 vv = *reinterpret_cast<const float4*>(kg + 768);
        *reinterpret_cast<float4*>(&vs[row * 100 + c4 * 4]) = vv;
    }
    __syncthreads();
#pragma unroll
    for (int p = 0; p < 12; p++) {
        const int idx = tid + p * 256;
        const int d = idx >> 5, nw = idx & 31;
        float v0 = vs[(2 * nw) * 100 + d];
        float v1 = vs[(2 * nw + 1) * 100 + d];
        uint32_t hh, ll;
        split2(v0, v1, hh, ll);
        const size_t w = (size_t)(bh * 96 + d) * 512 + nt * 32 + nw;
        g_vth[w] = hh; g_vtl[w] = ll;
    }
}

// ===========================================================================
//  fused attention. grid (8 qtiles of 128, 64 bh), 256 thr.
// ===========================================================================
constexpr int QSTR = 52;
constexpr int VSTR = 36;

// full 3-term QK (pass B)
DEV_INLINE void qk_mma(const uint32_t* Qh, const uint32_t* Ql,
                       const uint32_t* Kh, const uint32_t* Kl,
                       int rowb, int gq, int gt, float (*sacc)[4])
{
#pragma unroll
    for (int i = 0; i < 8; i++)
#pragma unroll
        for (int j = 0; j < 4; j++) sacc[i][j] = 0.f;
#pragma unroll
    for (int ks = 0; ks < 6; ks++) {
        const int cw = ks * 8 + gt;
        const int ra = (rowb + gq) * QSTR + cw;
        uint32_t ah[4], al[4];
        ah[0] = Qh[ra];            ah[1] = Qh[ra + 8 * QSTR];
        ah[2] = Qh[ra + 4];        ah[3] = Qh[ra + 8 * QSTR + 4];
        al[0] = Ql[ra];            al[1] = Ql[ra + 8 * QSTR];
        al[2] = Ql[ra + 4];        al[3] = Ql[ra + 8 * QSTR + 4];
#pragma unroll
        for (int nt = 0; nt < 8; nt++) {
            const int nb = (nt * 8 + gq) * QSTR + cw;
            uint32_t bh2[2] = {Kh[nb], Kh[nb + 4]};
            uint32_t bl2[2] = {Kl[nb], Kl[nb + 4]};
            mma16816(sacc[nt], ah, bh2);
            mma16816(sacc[nt], ah, bl2);
            mma16816(sacc[nt], al, bh2);
        }
    }
}

// hi-only QK (pass A stats: precision argument -> <=1e-5 effect on output)
DEV_INLINE void qk_mma_hi(const uint32_t* Qh, const uint32_t* Kh,
                          int rowb, int gq, int gt, float (*sacc)[4])
{
#pragma unroll
    for (int i = 0; i < 8; i++)
#pragma unroll
        for (int j = 0; j < 4; j++) sacc[i][j] = 0.f;
#pragma unroll
    for (int ks = 0; ks < 6; ks++) {
        const int cw = ks * 8 + gt;
        const int ra = (rowb + gq) * QSTR + cw;
        uint32_t ah[4];
        ah[0] = Qh[ra];            ah[1] = Qh[ra + 8 * QSTR];
        ah[2] = Qh[ra + 4];        ah[3] = Qh[ra + 8 * QSTR + 4];
#pragma unroll
        for (int nt = 0; nt < 8; nt++) {
            const int nb = (nt * 8 + gq) * QSTR + cw;
            uint32_t bh2[2] = {Kh[nb], Kh[nb + 4]};
            mma16816(sacc[nt], ah, bh2);
        }
    }
}

DEV_INLINE void online_upd(float& m, float& z, float s) {
    float nm = fmaxf(m, s);
    z = z * __expf(m - nm) + __expf(s - nm);
    m = nm;
}
DEV_INLINE void comb_mz(float& m, float& z, int d) {
    float mo = __shfl_xor_sync(0xffffffffu, m, d);
    float zo = __shfl_xor_sync(0xffffffffu, z, d);
    float nm = fmaxf(m, mo);
    z = z * __expf(m - nm) + zo * __expf(mo - nm);
    m = nm;
}

__global__ __launch_bounds__(256, 2) void attn_mma()
{
    extern __shared__ uint32_t smw[];
    uint32_t* Qh = smw;
    uint32_t* Ql = Qh + 128 * QSTR;
    uint32_t* Kh = Ql + 128 * QSTR;
    uint32_t* Kl = Kh + 64 * QSTR;
    uint32_t* Vh = Kl + 64 * QSTR;
    uint32_t* Vl = Vh + 96 * VSTR;

    const int qt = blockIdx.x, bh = blockIdx.y;
    const int b = bh >> 3, h = bh & 7;
    const int tid = threadIdx.x, lane = tid & 31, wid = tid >> 5;
    const int gq = lane >> 2, gt = lane & 3;
    const int rowb = wid * 16;

    {
        const uint4* qh4 = reinterpret_cast<const uint4*>(g_qh + (size_t)(bh * 1024 + qt * 128) * 48);
        const uint4* ql4 = reinterpret_cast<const uint4*>(g_ql + (size_t)(bh * 1024 + qt * 128) * 48);
#pragma unroll
        for (int p = 0; p < 6; p++) {
            const int idx = tid + p * 256;
            const int row = idx / 12, s = idx % 12;
            *reinterpret_cast<uint4*>(&Qh[row * QSTR + s * 4]) = qh4[row * 12 + s];
            *reinterpret_cast<uint4*>(&Ql[row * QSTR + s * 4]) = ql4[row * 12 + s];
        }
    }

    float m1[2] = {-1e30f, -1e30f}, z1[2] = {0.f, 0.f};
    float m2[2] = {-1e30f, -1e30f}, z2[2] = {0.f, 0.f};
    float sacc[8][4];

    // ================= PASS A: stats (hi-only) =================
    for (int c = 0; c < 16; c++) {
        __syncthreads();
        {
            const uint4* kh4 = reinterpret_cast<const uint4*>(g_kh + (size_t)(bh * 1024 + c * 64) * 48);
#pragma unroll
            for (int p = 0; p < 3; p++) {
                const int idx = tid + p * 256;
                const int row = idx / 12, s = idx % 12;
                *reinterpret_cast<uint4*>(&Kh[row * QSTR + s * 4]) = kh4[row * 12 + s];
            }
        }
        __syncthreads();
        qk_mma_hi(Qh, Kh, rowb, gq, gt, sacc);

        if (c == 0) {
#pragma unroll
            for (int nt = 0; nt < 8; nt++)
#pragma unroll
                for (int v = 0; v < 4; v++) {
                    const int col = nt * 8 + gt * 2 + (v & 1);
                    const int r = v >> 1;
                    if (col < 20) online_upd(m1[r], z1[r], sacc[nt][v]);
                    else          online_upd(m2[r], z2[r], sacc[nt][v]);
                }
        } else {
#pragma unroll
            for (int r = 0; r < 2; r++) {
                float lm = -1e30f;
#pragma unroll
                for (int nt = 0; nt < 8; nt++)
                    lm = fmaxf(lm, fmaxf(sacc[nt][r * 2], sacc[nt][r * 2 + 1]));
                const float nm = fmaxf(m2[r], lm);
                float zs = 0.f;
#pragma unroll
                for (int nt = 0; nt < 8; nt++)
                    zs += __expf(sacc[nt][r * 2] - nm) + __expf(sacc[nt][r * 2 + 1] - nm);
                z2[r] = z2[r] * __expf(m2[r] - nm) + zs;
                m2[r] = nm;
            }
        }
    }
#pragma unroll
    for (int r = 0; r < 2; r++) {
        comb_mz(m1[r], z1[r], 1); comb_mz(m1[r], z1[r], 2);
        comb_mz(m2[r], z2[r], 1); comb_mz(m2[r], z2[r], 2);
    }
    const float rz1[2] = {1.f / z1[0], 1.f / z1[1]};
    const float rz2[2] = {1.f / z2[0], 1.f / z2[1]};

    // ================= PASS B =================
    float vacc[12][4];
#pragma unroll
    for (int i = 0; i < 12; i++)
#pragma unroll
        for (int j = 0; j < 4; j++) vacc[i][j] = 0.f;
    float zf[2] = {0.f, 0.f};
    const int q0 = qt * 128 + rowb + gq;
    const uint32_t* mrow = g_mask + ((size_t)(bh << 10) + q0) * 32;

    for (int c = 0; c < 16; c++) {
        __syncthreads();
        {
            const uint4* kh4 = reinterpret_cast<const uint4*>(g_kh + (size_t)(bh * 1024 + c * 64) * 48);
            const uint4* kl4 = reinterpret_cast<const uint4*>(g_kl + (size_t)(bh * 1024 + c * 64) * 48);
#pragma unroll
            for (int p = 0; p < 3; p++) {
                const int idx = tid + p * 256;
                const int row = idx / 12, s = idx % 12;
                *reinterpret_cast<uint4*>(&Kh[row * QSTR + s * 4]) = kh4[row * 12 + s];
                *reinterpret_cast<uint4*>(&Kl[row * QSTR + s * 4]) = kl4[row * 12 + s];
            }
            const uint4* vh4 = reinterpret_cast<const uint4*>(g_vth + (size_t)(bh * 96) * 512);
            const uint4* vl4 = reinterpret_cast<const uint4*>(g_vtl + (size_t)(bh * 96) * 512);
#pragma unroll
            for (int p = 0; p < 3; p++) {
                const int idx = tid + p * 256;
                const int row = idx >> 3, s = idx & 7;
                *reinterpret_cast<uint4*>(&Vh[row * VSTR + s * 4]) = vh4[row * 128 + c * 8 + s];
                *reinterpret_cast<uint4*>(&Vl[row * VSTR + s * 4]) = vl4[row * 128 + c * 8 + s];
            }
        }
        __syncthreads();
        qk_mma(Qh, Ql, Kh, Kl, rowb, gq, gt, sacc);

        // mask words for this 64-col tile (rows q0, q0+8)
        const uint32_t mw0 = mrow[c * 2];
        const uint32_t mw1 = mrow[c * 2 + 1];
        const uint32_t mw2 = mrow[8 * 32 + c * 2];
        const uint32_t mw3 = mrow[8 * 32 + c * 2 + 1];

#pragma unroll
        for (int ks = 0; ks < 4; ks++) {
            uint32_t pah[4], pal[4];
#pragma unroll
            for (int half = 0; half < 2; half++) {
                const int nt = 2 * ks + half;
                float e[4];
#pragma unroll
                for (int v = 0; v < 4; v++) {
                    const int co = nt * 8 + gt * 2 + (v & 1);
                    const int r = v >> 1;
                    const bool cls = (c == 0) && (co < 20);
                    const float m  = cls ? m1[r] : m2[r];
                    const float rz = cls ? rz1[r] : rz2[r];
                    const float a  = __expf(sacc[nt][v] - m) * rz;
                    const uint32_t wsel = (nt < 4) ? (r ? mw2 : mw0) : (r ? mw3 : mw1);
                    const uint32_t keep = (wsel >> (co & 31)) & 1u;
                    const float ev = keep ? __expf(a - 1.f) : 0.f;
                    e[v] = ev;
                    zf[r] += ev;
                }
                uint32_t hh, ll;
                split2(e[0], e[1], hh, ll);
                pah[half * 2] = hh;     pal[half * 2] = ll;
                split2(e[2], e[3], hh, ll);
                pah[half * 2 + 1] = hh; pal[half * 2 + 1] = ll;
            }
            const int kw = ks * 8 + gt;
#pragma unroll
            for (int nt = 0; nt < 12; nt++) {
                const int nb = (nt * 8 + gq) * VSTR + kw;
                uint32_t bh2[2] = {Vh[nb], Vh[nb + 4]};
                uint32_t bl2[2] = {Vl[nb], Vl[nb + 4]};
                mma16816(vacc[nt], pah, bh2);
                mma16816(vacc[nt], pah, bl2);
                mma16816(vacc[nt], pal, bh2);
            }
        }
    }

#pragma unroll
    for (int r = 0; r < 2; r++) {
        zf[r] += __shfl_xor_sync(0xffffffffu, zf[r], 1);
        zf[r] += __shfl_xor_sync(0xffffffffu, zf[r], 2);
    }
    const float r0 = 1.f / zf[0], r1 = 1.f / zf[1];
    float* og = g_ao + (size_t)(b * 1024 + q0) * 768 + h * 96;
#pragma unroll
    for (int nt = 0; nt < 12; nt++) {
        const int col = nt * 8 + gt * 2;
        *reinterpret_cast<float2*>(og + col) =
            make_float2(vacc[nt][0] * r0, vacc[nt][1] * r0);
        *reinterpret_cast<float2*>(og + 8 * 768 + col) =
            make_float2(vacc[nt][2] * r1, vacc[nt][3] * r1);
    }
}

// ---------------------------------------------------------------------------
extern "C" void kernel_launch(void* const* d_in, const int* in_sizes, int n_in,
                              void* d_out, int out_size)
{
    const float* input_query = (const float*)d_in[0];
    const float* input_key   = (const float*)d_in[1];
    const float* Wq          = (const float*)d_in[2];
    const float* Wkv         = (const float*)d_in[3];
    // d_in[4] = Wcls  -- provably unused
    const float* Wproj       = (const float*)d_in[5];
    const float* bproj       = (const float*)d_in[6];
    float* out = (float*)d_out;

    float *qp, *kvp, *aop;
    cudaGetSymbolAddress((void**)&qp,  g_q);
    cudaGetSymbolAddress((void**)&kvp, g_kv);
    cudaGetSymbolAddress((void**)&aop, g_ao);

    const int attn_smem = (128 * QSTR * 2 + 64 * QSTR * 2 + 96 * VSTR * 2) * 4;
    cudaFuncSetAttribute(attn_mma, cudaFuncAttributeMaxDynamicSharedMemorySize, attn_smem);

    // mask words: 2,097,152 total. Wq gemm gets [0, 1048576) stride 98304 (24 iters),
    // Wkv gemm gets [1048576, 2097152) stride 196608.
    mma_gemm<false><<<dim3(6, 64), 256>>>(input_query, Wq, nullptr, qp, 8192, 768, 768,
                                          0u, 1048576u, 98304u);
    mma_gemm<false><<<dim3(12, 64), 256>>>(input_key, Wkv, nullptr, kvp, 8192, 1536, 768,
                                           1048576u, 2097152u, 196608u);
    prep_kernel<<<dim3(16, 64), 256>>>();
    attn_mma<<<dim3(8, 64), 256, attn_smem>>>();
    mma_gemm<true><<<dim3(6, 64), 256>>>(aop, Wproj, bproj, out, 8192, 768, 768,
                                         0u, 0u, 0u);
}